// round 7
// baseline (speedup 1.0000x reference)
#include <cuda_runtime.h>
#include <cuda_fp16.h>
#include <math.h>

// ---------------- problem constants ----------------
#define NNODES 2048
#define SEQ    512
#define HID    256
#define NFEAT  9
#define NEDGE  65536
#define NLAY   3
#define STEPA  14

#define H   2048          // GRU hidden = NNODES
#define T   256           // GRU time steps = HID
#define GH  6144          // 3*H

#define NBLK 128          // persistent CTAs (co-resident)
#define IPB  16           // hidden units per CTA
#define NGRP 16           // producer groups (8 CTAs each, 128 h units per group)
#define SCAN_THREADS 512
#define PRE_THREADS  512

// ---------------- scratch (device globals; no cudaMalloc allowed) ----------------
__device__ float    g_xs[NNODES*SEQ];       // conv output (n, s)
__device__ float    g_h0[NNODES*HID];       // pre-GCN h
__device__ float    g_hagg[NNODES*HID];     // GCN aggregate
__device__ float    g_deg[NNODES];
__device__ float    g_dinv[NNODES];
__device__ float    g_gi[T*GH];             // precomputed input gates
__device__ __align__(16) __half g_ht[(T+1)*H]; // per-step hidden states (fp16), ht[0]=0
__device__ unsigned g_flag[(T+1)*NGRP];     // per-(step,group) ready counters
__device__ unsigned g_pbar[8];              // phase barrier counters (preproc)

// ---------------- small helpers ----------------
__device__ __forceinline__ void bar_arrive(unsigned* p) {
    asm volatile("red.release.gpu.global.add.u32 [%0], 1;" :: "l"(p) : "memory");
}
__device__ __forceinline__ unsigned bar_ld_acq(const unsigned* p) {
    unsigned v;
    asm volatile("ld.acquire.gpu.global.u32 %0, [%1];" : "=r"(v) : "l"(p) : "memory");
    return v;
}
__device__ __forceinline__ void gbar(unsigned* ctr) {
    __syncthreads();
    if (threadIdx.x == 0) {
        bar_arrive(ctr);
        while (bar_ld_acq(ctr) < NBLK) {}
    }
    __syncthreads();
}
__device__ __forceinline__ void mma16816(float* d, const unsigned* a, const unsigned* b) {
    asm volatile("mma.sync.aligned.m16n8k16.row.col.f32.f16.f16.f32 "
                 "{%0,%1,%2,%3},{%4,%5,%6,%7},{%8,%9},{%0,%1,%2,%3};"
                 : "+f"(d[0]), "+f"(d[1]), "+f"(d[2]), "+f"(d[3])
                 : "r"(a[0]), "r"(a[1]), "r"(a[2]), "r"(a[3]),
                   "r"(b[0]), "r"(b[1]));
}
__device__ __forceinline__ unsigned pack_h2(float x, float y) {
    __half2 h = __floats2half2_rn(x, y);
    return *(unsigned*)&h;
}

// ---------------- 0) reset preproc barrier counters (graph-replay safe) ----------
__global__ void k_zero0() {
    if (threadIdx.x < 8) g_pbar[threadIdx.x] = 0u;
}

// ================= 1) fused preprocessing (persistent, 128 CTAs) =================
__global__ void __launch_bounds__(PRE_THREADS)
k_pre(const float* __restrict__ x,  const float* __restrict__ cw,
      const float* __restrict__ cb, const int*   __restrict__ ei,
      const float* __restrict__ ew, const float* __restrict__ gw,
      const float* __restrict__ gb) {
    __shared__ float As[16][64];
    __shared__ float Bs[16][68];   // 272B row stride: 16B-aligned rows, pad vs conflicts
    const int b = blockIdx.x, tid = threadIdx.x;
    const int gt = b * PRE_THREADS + tid;
    const int GT = NBLK * PRE_THREADS;            // 65536

    // ---- P0: 1x1 conv + zero hagg + deg=1 ----
    {
        float bias = cb[0];
        float w[NFEAT];
#pragma unroll
        for (int f = 0; f < NFEAT; f++) w[f] = cw[f];
        const int n4 = NNODES * SEQ / 4;
        const float4* X = (const float4*)x;
        for (int i = gt; i < n4; i += GT) {
            float4 acc = make_float4(bias, bias, bias, bias);
#pragma unroll
            for (int f = 0; f < NFEAT; f++) {
                float4 v = X[(size_t)f * n4 + i];
                acc.x = fmaf(w[f], v.x, acc.x); acc.y = fmaf(w[f], v.y, acc.y);
                acc.z = fmaf(w[f], v.z, acc.z); acc.w = fmaf(w[f], v.w, acc.w);
            }
            ((float4*)g_xs)[i] = acc;
        }
        float4 z4 = make_float4(0.f, 0.f, 0.f, 0.f);
        for (int i = gt; i < NNODES * HID / 4; i += GT) ((float4*)g_hagg)[i] = z4;
        for (int i = gt; i < NNODES; i += GT) g_deg[i] = 1.0f;
    }
    gbar(&g_pbar[0]);

    // ---- P1: degree atomics + h0 = xs @ gcn_w (one 64x64 tile per CTA) ----
    for (int e = gt; e < NEDGE; e += GT)
        atomicAdd(&g_deg[ei[NEDGE + e]], ew[e]);
    {
        const int bm = (b >> 2) * 64, bn = (b & 3) * 64;
        const int tx = tid & 15, ty = tid >> 4;
        float acc[2][4] = {};
        for (int k0 = 0; k0 < SEQ; k0 += 16) {
            {   // A: 64 rows x 16 k, transposed into As[k][m]
                int ar = tid >> 3, ac = (tid & 7) * 2;
                float2 v = *(const float2*)&g_xs[(bm + ar) * SEQ + k0 + ac];
                As[ac][ar] = v.x; As[ac + 1][ar] = v.y;
            }
            {   // B: 16 k x 64 n
                int br = tid >> 5, bc = (tid & 31) * 2;
                float2 v = *(const float2*)&gw[(k0 + br) * HID + bn + bc];
                Bs[br][bc] = v.x; Bs[br][bc + 1] = v.y;
            }
            __syncthreads();
#pragma unroll
            for (int kk = 0; kk < 16; kk++) {
                float a0 = As[kk][ty * 2], a1 = As[kk][ty * 2 + 1];
                float4 bb = *(const float4*)&Bs[kk][tx * 4];
                acc[0][0] = fmaf(a0, bb.x, acc[0][0]); acc[0][1] = fmaf(a0, bb.y, acc[0][1]);
                acc[0][2] = fmaf(a0, bb.z, acc[0][2]); acc[0][3] = fmaf(a0, bb.w, acc[0][3]);
                acc[1][0] = fmaf(a1, bb.x, acc[1][0]); acc[1][1] = fmaf(a1, bb.y, acc[1][1]);
                acc[1][2] = fmaf(a1, bb.z, acc[1][2]); acc[1][3] = fmaf(a1, bb.w, acc[1][3]);
            }
            __syncthreads();
        }
#pragma unroll
        for (int i = 0; i < 2; i++)
#pragma unroll
            for (int j = 0; j < 4; j++)
                g_h0[(bm + ty * 2 + i) * HID + bn + tx * 4 + j] = acc[i][j];
    }
    gbar(&g_pbar[1]);

    // ---- P2: dinv ----
    for (int i = gt; i < NNODES; i += GT)
        g_dinv[i] = rsqrtf(fmaxf(g_deg[i], 1e-12f));
    gbar(&g_pbar[2]);

    // ---- P3: edge aggregation (one warp -> 32 edges) ----
    {
        const int gw2 = gt >> 5, lane = tid & 31;
        for (int e = gw2 * 32; e < gw2 * 32 + 32; e++) {
            int row = ei[e], col = ei[NEDGE + e];
            float norm = g_dinv[row] * ew[e] * g_dinv[col];
            const float* hs = g_h0 + (size_t)row * HID;
            float* hd = g_hagg + (size_t)col * HID;
#pragma unroll
            for (int j = 0; j < HID / 32; j++)
                atomicAdd(&hd[lane + 32 * j], norm * hs[lane + 32 * j]);
        }
    }
    gbar(&g_pbar[3]);

    // ---- P4: self-loop + bias + relu + transpose into g_ht[1..T] (fp16) ----
    for (int i = gt; i < NNODES * HID; i += GT) {
        int n = i & (NNODES - 1), c = i >> 11;
        float d = g_dinv[n];
        float v = g_hagg[n * HID + c] + d * d * g_h0[n * HID + c] + gb[c];
        g_ht[(size_t)(1 + c) * H + n] = __float2half(fmaxf(v, 0.0f));
    }
}

// ---------------- 2) gi = seq @ wih.T + bih  via fp16 tensor cores ----------------
// seq = g_ht[1..T] (fp16, time-major)
#define GI_LD 72
__global__ void __launch_bounds__(256) k_gi(const float* __restrict__ B,
                                            const float* __restrict__ bih) {
    __shared__ alignas(16) __half sA[64 * GI_LD];
    __shared__ alignas(16) __half sB[128 * GI_LD];
    const int bm = blockIdx.y * 64, bn = blockIdx.x * 128;
    const int tid = threadIdx.x, lane = tid & 31, warp = tid >> 5;
    const int wm = warp >> 2, wn = warp & 3;
    float acc[2][4][4] = {};

    for (int k0 = 0; k0 < H; k0 += 64) {
#pragma unroll
        for (int i = 0; i < 2; i++) {                       // A tile 64x64 (raw fp16 copy)
            int idx = tid + i * 256;
            int r = idx >> 3, c8 = idx & 7;
            uint4 v = *(const uint4*)(g_ht + (size_t)(1 + bm + r) * H + k0 + c8 * 8);
            *(uint4*)&sA[r * GI_LD + c8 * 8] = v;
        }
#pragma unroll
        for (int i = 0; i < 8; i++) {                       // B tile 128x64 (fp32 -> fp16)
            int idx = tid + i * 256;
            int r = idx >> 4, c4 = idx & 15;
            float4 v = *(const float4*)&B[(size_t)(bn + r) * H + k0 + c4 * 4];
            *(__half2*)&sB[r * GI_LD + c4 * 4]     = __floats2half2_rn(v.x, v.y);
            *(__half2*)&sB[r * GI_LD + c4 * 4 + 2] = __floats2half2_rn(v.z, v.w);
        }
        __syncthreads();
#pragma unroll
        for (int ks = 0; ks < 4; ks++) {
            unsigned a[2][4], b[4][2];
#pragma unroll
            for (int mt = 0; mt < 2; mt++) {
                int r = wm * 32 + mt * 16 + (lane >> 2);
                int c = ks * 16 + (lane & 3) * 2;
                a[mt][0] = *(const unsigned*)&sA[r * GI_LD + c];
                a[mt][1] = *(const unsigned*)&sA[(r + 8) * GI_LD + c];
                a[mt][2] = *(const unsigned*)&sA[r * GI_LD + c + 8];
                a[mt][3] = *(const unsigned*)&sA[(r + 8) * GI_LD + c + 8];
            }
#pragma unroll
            for (int nt = 0; nt < 4; nt++) {
                int r = wn * 32 + nt * 8 + (lane >> 2);
                int c = ks * 16 + (lane & 3) * 2;
                b[nt][0] = *(const unsigned*)&sB[r * GI_LD + c];
                b[nt][1] = *(const unsigned*)&sB[r * GI_LD + c + 8];
            }
#pragma unroll
            for (int mt = 0; mt < 2; mt++)
#pragma unroll
                for (int nt = 0; nt < 4; nt++)
                    mma16816(acc[mt][nt], a[mt], b[nt]);
        }
        __syncthreads();
    }
#pragma unroll
    for (int mt = 0; mt < 2; mt++) {
        int r0 = bm + wm * 32 + mt * 16 + (lane >> 2);
#pragma unroll
        for (int nt = 0; nt < 4; nt++) {
            int g = bn + wn * 32 + nt * 8 + (lane & 3) * 2;
            float2 bb = *(const float2*)&bih[g];
            float* c4 = acc[mt][nt];
            *(float2*)&g_gi[r0 * GH + g]       = make_float2(c4[0] + bb.x, c4[1] + bb.y);
            *(float2*)&g_gi[(r0 + 8) * GH + g] = make_float2(c4[2] + bb.x, c4[3] + bb.y);
        }
    }
}

// ---------------- 3) init h(0)=0 and ready-flags for this layer ----------------
__global__ void k_zero2() {
    int i = blockIdx.x * blockDim.x + threadIdx.x;
    if (i < H) g_ht[i] = __float2half(0.0f);
    if (i < (T + 1) * NGRP) g_flag[i] = (i < NGRP) ? 8u : 0u;  // step 0 pre-ready
}

// ---------------- 4) persistent GRU scan — dataflow-pipelined, no global barrier --
// 128 CTAs x 512 thr. CTA b owns hidden units [16b,16b+16). whh lives as HMMA
// A-fragments in registers. h(t) lives in per-step buffer g_ht[t]; group g
// (h cols 128g..128g+128, produced by CTAs 8g..8g+7) publishes a counter; warp w
// waits only for its group counter, so waiting overlaps other warps' MMAs and
// there is NO full-GPU barrier per step.
__global__ void __launch_bounds__(SCAN_THREADS, 1)
k_scan(const float* __restrict__ whh, const float* __restrict__ bhh) {
    __shared__ alignas(16) __half sh[H];
    __shared__ float spart[2][16][48];

    const int b = blockIdx.x, tid = threadIdx.x;
    const int warp = tid >> 5, lane = tid & 31;
    const int qid = lane >> 2, tg = lane & 3;
    const int kbase = warp * 128;                 // this warp's K range (128 cols)
    const int mygrp = b >> 3;
    const int ig = b * IPB + lane;                // valid for lane<16 in warp 0

    // ---- one-time: load this thread's A fragments (fp16) ----
    unsigned aw[8][3][4];
    {
        const int r0 = b * IPB + qid;             // rows r0, r0+8 within each gate
#pragma unroll
        for (int kt = 0; kt < 8; kt++) {
            const int c = kbase + kt * 16 + tg * 2;
#pragma unroll
            for (int g = 0; g < 3; g++) {
                const float* W0 = whh + (size_t)(g * H + r0) * H;
                const float* W1 = W0 + 8 * (size_t)H;
                float2 v;
                v = *(const float2*)(W0 + c);     aw[kt][g][0] = pack_h2(v.x, v.y);
                v = *(const float2*)(W1 + c);     aw[kt][g][1] = pack_h2(v.x, v.y);
                v = *(const float2*)(W0 + c + 8); aw[kt][g][2] = pack_h2(v.x, v.y);
                v = *(const float2*)(W1 + c + 8); aw[kt][g][3] = pack_h2(v.x, v.y);
            }
        }
    }
    // gate-thread constants + running h (fp32, pre-quantization)
    float hold = 0.0f, bR = 0.f, bZ = 0.f, bN = 0.f;
    if (warp == 0 && lane < IPB) {
        bR = bhh[ig]; bZ = bhh[H + ig]; bN = bhh[2 * H + ig];
    }

#pragma unroll 1
    for (int t = 0; t < T; t++) {
        // prefetch this step's input gates (independent of h; overlaps the wait)
        float gir = 0.f, giz = 0.f, gin = 0.f;
        if (warp == 0 && lane < IPB) {
            const float* git = g_gi + (size_t)t * GH;
            gir = __ldg(git + ig); giz = __ldg(git + H + ig); gin = __ldg(git + 2 * H + ig);
        }

        // wait until this warp's h-slice for step t is published (8 producer CTAs)
        {
            const unsigned* fp = &g_flag[t * NGRP + warp];
            while (bar_ld_acq(fp) < 8u) {}
        }
        // stage the 128-col slice (warp-private; acquire above orders the ldcg)
        {
            uint2 hv = __ldcg((const uint2*)(g_ht + (size_t)t * H + kbase) + lane);
            *((uint2*)(sh + kbase) + lane) = hv;
        }
        __syncwarp();

        float d[3][4];
#pragma unroll
        for (int g = 0; g < 3; g++) { d[g][0] = d[g][1] = d[g][2] = d[g][3] = 0.f; }
#pragma unroll
        for (int kt = 0; kt < 8; kt++) {
            unsigned bb[2];
            bb[0] = *(const unsigned*)&sh[kbase + kt * 16 + tg * 2];
            bb[1] = *(const unsigned*)&sh[kbase + kt * 16 + tg * 2 + 8];
            mma16816(d[0], aw[kt][0], bb);
            mma16816(d[1], aw[kt][1], bb);
            mma16816(d[2], aw[kt][2], bb);
        }
        const int par = t & 1;
        if (tg == 0) {
#pragma unroll
            for (int g = 0; g < 3; g++) {
                spart[par][warp][g * 16 + qid]     = d[g][0];
                spart[par][warp][g * 16 + qid + 8] = d[g][2];
            }
        }
        __syncthreads();   // spart[par] complete; runahead provably <= 1 step

        if (warp == 0) {
            if (lane < IPB) {
                float ghr = 0.f, ghz = 0.f, ghn = 0.f;
#pragma unroll
                for (int w2 = 0; w2 < 16; w2++) {
                    ghr += spart[par][w2][lane];
                    ghz += spart[par][w2][16 + lane];
                    ghn += spart[par][w2][32 + lane];
                }
                float rr = 1.0f / (1.0f + expf(-(gir + ghr + bR)));
                float zz = 1.0f / (1.0f + expf(-(giz + ghz + bZ)));
                float nn = tanhf(gin + rr * (ghn + bN));
                float hnew = (1.0f - zz) * nn + zz * hold;
                hold = hnew;
                g_ht[(size_t)(t + 1) * H + ig] = __float2half(hnew);
            }
            __syncwarp();
            if (lane == 0)
                bar_arrive(&g_flag[(t + 1) * NGRP + mygrp]);  // release: orders h stores
        }
    }
}

// ---------------- 5) final linear: out[n] = h[:,n] @ lin_w + lin_b ----------------
__global__ void k_final(const float* __restrict__ lw, const float* __restrict__ lb,
                        float* __restrict__ out) {
    __shared__ float s[T];
    int n = blockIdx.x, tid = threadIdx.x;   // 256 threads
    s[tid] = __half2float(g_ht[(size_t)(tid + 1) * H + n]);
    __syncthreads();
    if (tid < STEPA) {
        float a = lb[tid];
#pragma unroll 8
        for (int t = 0; t < T; t++) a = fmaf(s[t], lw[t * STEPA + tid], a);
        out[n * STEPA + tid] = a;
    }
}

// ---------------- launch ----------------
extern "C" void kernel_launch(void* const* d_in, const int* in_sizes, int n_in,
                              void* d_out, int out_size) {
    const float* x      = (const float*)d_in[0];
    const int*   ei     = (const int*)  d_in[1];
    const float* ew     = (const float*)d_in[2];
    const float* cnn_w  = (const float*)d_in[3];
    const float* cnn_b  = (const float*)d_in[4];
    const float* gcn_w  = (const float*)d_in[5];
    const float* gcn_b  = (const float*)d_in[6];
    const float* wih    = (const float*)d_in[7];
    const float* whh    = (const float*)d_in[8];
    const float* bih    = (const float*)d_in[9];
    const float* bhh    = (const float*)d_in[10];
    const float* lin_w  = (const float*)d_in[11];
    const float* lin_b  = (const float*)d_in[12];
    float* out = (float*)d_out;

    k_zero0<<<1, 32>>>();                      // replay-safe preproc barrier reset
    k_pre<<<NBLK, PRE_THREADS>>>(x, cnn_w, cnn_b, ei, ew, gcn_w, gcn_b);

    for (int l = 0; l < NLAY; l++) {
        dim3 grid(GH / 128, T / 64);
        k_gi<<<grid, 256>>>(wih + (size_t)l * GH * H, bih + l * GH);
        k_zero2<<<17, 256>>>();
        k_scan<<<NBLK, SCAN_THREADS>>>(whh + (size_t)l * GH * H, bhh + l * GH);
    }

    k_final<<<NNODES, T>>>(lin_w, lin_b, out);
}

// round 8
// speedup vs baseline: 1.6452x; 1.6452x over previous
#include <cuda_runtime.h>
#include <cuda_fp16.h>
#include <math.h>

// ---------------- problem constants ----------------
#define NNODES 2048
#define SEQ    512
#define HID    256
#define NFEAT  9
#define NEDGE  65536
#define NLAY   3
#define STEPA  14

#define H   2048          // GRU hidden = NNODES
#define T   256           // GRU time steps = HID
#define GH  6144          // 3*H

#define NBLK 128          // persistent CTAs (co-resident)
#define IPB  16           // hidden units per CTA
#define SCAN_THREADS 512
#define PRE_THREADS  512

// ---------------- scratch (device globals; no cudaMalloc allowed) ----------------
__device__ float    g_xs[NNODES*SEQ];       // conv output (n, s)
__device__ float    g_h0[NNODES*HID];       // pre-GCN h
__device__ float    g_hagg[NNODES*HID];     // GCN aggregate
__device__ float    g_deg[NNODES];
__device__ float    g_dinv[NNODES];
__device__ float    g_gi[T*GH];             // precomputed input gates
__device__ __align__(16) __half g_ht[(T+1)*H]; // per-step hidden states (fp16), ht[0]=0
__device__ unsigned g_bar[T+1];             // per-step arrival counters (monotonic over layers)
__device__ unsigned g_pbar[8];              // phase barrier counters (preproc)

// ---------------- small helpers ----------------
__device__ __forceinline__ void bar_arrive(unsigned* p) {
    asm volatile("red.release.gpu.global.add.u32 [%0], 1;" :: "l"(p) : "memory");
}
__device__ __forceinline__ unsigned bar_ld_acq(const unsigned* p) {
    unsigned v;
    asm volatile("ld.acquire.gpu.global.u32 %0, [%1];" : "=r"(v) : "l"(p) : "memory");
    return v;
}
__device__ __forceinline__ void gbar(unsigned* ctr) {
    __syncthreads();
    if (threadIdx.x == 0) {
        bar_arrive(ctr);
        while (bar_ld_acq(ctr) < NBLK) {}
    }
    __syncthreads();
}
__device__ __forceinline__ void mma16816(float* d, const unsigned* a, const unsigned* b) {
    asm volatile("mma.sync.aligned.m16n8k16.row.col.f32.f16.f16.f32 "
                 "{%0,%1,%2,%3},{%4,%5,%6,%7},{%8,%9},{%0,%1,%2,%3};"
                 : "+f"(d[0]), "+f"(d[1]), "+f"(d[2]), "+f"(d[3])
                 : "r"(a[0]), "r"(a[1]), "r"(a[2]), "r"(a[3]),
                   "r"(b[0]), "r"(b[1]));
}
__device__ __forceinline__ unsigned pack_h2(float x, float y) {
    __half2 h = __floats2half2_rn(x, y);
    return *(unsigned*)&h;
}
#define BAR_ARRIVE_N(id) asm volatile("bar.arrive %0, %1;" :: "r"(id), "r"(SCAN_THREADS))
#define BAR_SYNC_N(id)   asm volatile("bar.sync %0, %1;"   :: "r"(id), "r"(SCAN_THREADS) : "memory")

// ---------------- 0) replay-safe reset: pbar, step counters, h(0)=0 ------------
__global__ void k_zero0() {
    int i = blockIdx.x * blockDim.x + threadIdx.x;   // 2048 threads
    if (i < 8) g_pbar[i] = 0u;
    if (i <= T) g_bar[i] = 0u;
    if (i < H) g_ht[i] = __float2half(0.0f);
}

// ================= 1) fused preprocessing (persistent, 128 CTAs) =================
__global__ void __launch_bounds__(PRE_THREADS)
k_pre(const float* __restrict__ x,  const float* __restrict__ cw,
      const float* __restrict__ cb, const int*   __restrict__ ei,
      const float* __restrict__ ew, const float* __restrict__ gw,
      const float* __restrict__ gb) {
    __shared__ float As[16][64];
    __shared__ float Bs[16][68];   // 272B row stride: 16B-aligned rows, pad vs conflicts
    const int b = blockIdx.x, tid = threadIdx.x;
    const int gt = b * PRE_THREADS + tid;
    const int GT = NBLK * PRE_THREADS;            // 65536

    // ---- P0: 1x1 conv + zero hagg + deg=1 ----
    {
        float bias = cb[0];
        float w[NFEAT];
#pragma unroll
        for (int f = 0; f < NFEAT; f++) w[f] = cw[f];
        const int n4 = NNODES * SEQ / 4;
        const float4* X = (const float4*)x;
        for (int i = gt; i < n4; i += GT) {
            float4 acc = make_float4(bias, bias, bias, bias);
#pragma unroll
            for (int f = 0; f < NFEAT; f++) {
                float4 v = X[(size_t)f * n4 + i];
                acc.x = fmaf(w[f], v.x, acc.x); acc.y = fmaf(w[f], v.y, acc.y);
                acc.z = fmaf(w[f], v.z, acc.z); acc.w = fmaf(w[f], v.w, acc.w);
            }
            ((float4*)g_xs)[i] = acc;
        }
        float4 z4 = make_float4(0.f, 0.f, 0.f, 0.f);
        for (int i = gt; i < NNODES * HID / 4; i += GT) ((float4*)g_hagg)[i] = z4;
        for (int i = gt; i < NNODES; i += GT) g_deg[i] = 1.0f;
    }
    gbar(&g_pbar[0]);

    // ---- P1: degree atomics + h0 = xs @ gcn_w (one 64x64 tile per CTA) ----
    for (int e = gt; e < NEDGE; e += GT)
        atomicAdd(&g_deg[ei[NEDGE + e]], ew[e]);
    {
        const int bm = (b >> 2) * 64, bn = (b & 3) * 64;
        const int tx = tid & 15, ty = tid >> 4;
        float acc[2][4] = {};
        for (int k0 = 0; k0 < SEQ; k0 += 16) {
            {   // A: 64 rows x 16 k, transposed into As[k][m]
                int ar = tid >> 3, ac = (tid & 7) * 2;
                float2 v = *(const float2*)&g_xs[(bm + ar) * SEQ + k0 + ac];
                As[ac][ar] = v.x; As[ac + 1][ar] = v.y;
            }
            {   // B: 16 k x 64 n
                int br = tid >> 5, bc = (tid & 31) * 2;
                float2 v = *(const float2*)&gw[(k0 + br) * HID + bn + bc];
                Bs[br][bc] = v.x; Bs[br][bc + 1] = v.y;
            }
            __syncthreads();
#pragma unroll
            for (int kk = 0; kk < 16; kk++) {
                float a0 = As[kk][ty * 2], a1 = As[kk][ty * 2 + 1];
                float4 bb = *(const float4*)&Bs[kk][tx * 4];
                acc[0][0] = fmaf(a0, bb.x, acc[0][0]); acc[0][1] = fmaf(a0, bb.y, acc[0][1]);
                acc[0][2] = fmaf(a0, bb.z, acc[0][2]); acc[0][3] = fmaf(a0, bb.w, acc[0][3]);
                acc[1][0] = fmaf(a1, bb.x, acc[1][0]); acc[1][1] = fmaf(a1, bb.y, acc[1][1]);
                acc[1][2] = fmaf(a1, bb.z, acc[1][2]); acc[1][3] = fmaf(a1, bb.w, acc[1][3]);
            }
            __syncthreads();
        }
#pragma unroll
        for (int i = 0; i < 2; i++)
#pragma unroll
            for (int j = 0; j < 4; j++)
                g_h0[(bm + ty * 2 + i) * HID + bn + tx * 4 + j] = acc[i][j];
    }
    gbar(&g_pbar[1]);

    // ---- P2: dinv ----
    for (int i = gt; i < NNODES; i += GT)
        g_dinv[i] = rsqrtf(fmaxf(g_deg[i], 1e-12f));
    gbar(&g_pbar[2]);

    // ---- P3: edge aggregation (one warp -> 32 edges) ----
    {
        const int gw2 = gt >> 5, lane = tid & 31;
        for (int e = gw2 * 32; e < gw2 * 32 + 32; e++) {
            int row = ei[e], col = ei[NEDGE + e];
            float norm = g_dinv[row] * ew[e] * g_dinv[col];
            const float* hs = g_h0 + (size_t)row * HID;
            float* hd = g_hagg + (size_t)col * HID;
#pragma unroll
            for (int j = 0; j < HID / 32; j++)
                atomicAdd(&hd[lane + 32 * j], norm * hs[lane + 32 * j]);
        }
    }
    gbar(&g_pbar[3]);

    // ---- P4: self-loop + bias + relu + transpose into g_ht[1..T] (fp16) ----
    for (int i = gt; i < NNODES * HID; i += GT) {
        int n = i & (NNODES - 1), c = i >> 11;
        float d = g_dinv[n];
        float v = g_hagg[n * HID + c] + d * d * g_h0[n * HID + c] + gb[c];
        g_ht[(size_t)(1 + c) * H + n] = __float2half(fmaxf(v, 0.0f));
    }
}

// ---------------- 2) gi = seq @ wih.T + bih  via fp16 tensor cores ----------------
// seq = g_ht[1..T] (fp16, time-major)
#define GI_LD 72
__global__ void __launch_bounds__(256) k_gi(const float* __restrict__ B,
                                            const float* __restrict__ bih) {
    __shared__ alignas(16) __half sA[64 * GI_LD];
    __shared__ alignas(16) __half sB[128 * GI_LD];
    const int bm = blockIdx.y * 64, bn = blockIdx.x * 128;
    const int tid = threadIdx.x, lane = tid & 31, warp = tid >> 5;
    const int wm = warp >> 2, wn = warp & 3;
    float acc[2][4][4] = {};

    for (int k0 = 0; k0 < H; k0 += 64) {
#pragma unroll
        for (int i = 0; i < 2; i++) {                       // A tile 64x64 (raw fp16 copy)
            int idx = tid + i * 256;
            int r = idx >> 3, c8 = idx & 7;
            uint4 v = *(const uint4*)(g_ht + (size_t)(1 + bm + r) * H + k0 + c8 * 8);
            *(uint4*)&sA[r * GI_LD + c8 * 8] = v;
        }
#pragma unroll
        for (int i = 0; i < 8; i++) {                       // B tile 128x64 (fp32 -> fp16)
            int idx = tid + i * 256;
            int r = idx >> 4, c4 = idx & 15;
            float4 v = *(const float4*)&B[(size_t)(bn + r) * H + k0 + c4 * 4];
            *(__half2*)&sB[r * GI_LD + c4 * 4]     = __floats2half2_rn(v.x, v.y);
            *(__half2*)&sB[r * GI_LD + c4 * 4 + 2] = __floats2half2_rn(v.z, v.w);
        }
        __syncthreads();
#pragma unroll
        for (int ks = 0; ks < 4; ks++) {
            unsigned a[2][4], b[4][2];
#pragma unroll
            for (int mt = 0; mt < 2; mt++) {
                int r = wm * 32 + mt * 16 + (lane >> 2);
                int c = ks * 16 + (lane & 3) * 2;
                a[mt][0] = *(const unsigned*)&sA[r * GI_LD + c];
                a[mt][1] = *(const unsigned*)&sA[(r + 8) * GI_LD + c];
                a[mt][2] = *(const unsigned*)&sA[r * GI_LD + c + 8];
                a[mt][3] = *(const unsigned*)&sA[(r + 8) * GI_LD + c + 8];
            }
#pragma unroll
            for (int nt = 0; nt < 4; nt++) {
                int r = wn * 32 + nt * 8 + (lane >> 2);
                int c = ks * 16 + (lane & 3) * 2;
                b[nt][0] = *(const unsigned*)&sB[r * GI_LD + c];
                b[nt][1] = *(const unsigned*)&sB[r * GI_LD + c + 8];
            }
#pragma unroll
            for (int mt = 0; mt < 2; mt++)
#pragma unroll
                for (int nt = 0; nt < 4; nt++)
                    mma16816(acc[mt][nt], a[mt], b[nt]);
        }
        __syncthreads();
    }
#pragma unroll
    for (int mt = 0; mt < 2; mt++) {
        int r0 = bm + wm * 32 + mt * 16 + (lane >> 2);
#pragma unroll
        for (int nt = 0; nt < 4; nt++) {
            int g = bn + wn * 32 + nt * 8 + (lane & 3) * 2;
            float2 bb = *(const float2*)&bih[g];
            float* c4 = acc[mt][nt];
            *(float2*)&g_gi[r0 * GH + g]       = make_float2(c4[0] + bb.x, c4[1] + bb.y);
            *(float2*)&g_gi[(r0 + 8) * GH + g] = make_float2(c4[2] + bb.x, c4[3] + bb.y);
        }
    }
}

// ---------------- 3) persistent GRU scan — HMMA + named-barrier pipeline ----------
// 128 CTAs x 512 thr. CTA b owns hidden units [16b,16b+16); whh lives as HMMA
// A-fragments in registers. Per step: each warp stages its OWN 256B h-slice
// (syncwarp only), MMAs, stores partials (parity-buffered, transposed), then
// bar.arrive(1) + bar.sync(2). Warp 0: bar.sync(1) -> vector-reduce -> gate math
// -> publish 32B h -> ONE red.release + ONE acquire-poll per CTA -> bar.arrive(2).
// Step counters are monotonic across layers: target = NBLK*(layer+1); no reset
// kernel between layers.
__global__ void __launch_bounds__(SCAN_THREADS, 1)
k_scan(const float* __restrict__ whh, const float* __restrict__ bhh, int layer) {
    __shared__ alignas(16) __half sh[H];
    __shared__ alignas(16) float spt[2][48][20];   // [parity][row][warp], padded

    const int b = blockIdx.x, tid = threadIdx.x;
    const int warp = tid >> 5, lane = tid & 31;
    const int qid = lane >> 2, tg = lane & 3;
    const int kbase = warp * 128;                 // this warp's K range (128 cols)
    const int ig = b * IPB + lane;                // valid for lane<16 in warp 0
    const unsigned target = (unsigned)NBLK * (unsigned)(layer + 1);

    // ---- one-time: load this thread's A fragments (fp16) ----
    unsigned aw[8][3][4];
    {
        const int r0 = b * IPB + qid;             // rows r0, r0+8 within each gate
#pragma unroll
        for (int kt = 0; kt < 8; kt++) {
            const int c = kbase + kt * 16 + tg * 2;
#pragma unroll
            for (int g = 0; g < 3; g++) {
                const float* W0 = whh + (size_t)(g * H + r0) * H;
                const float* W1 = W0 + 8 * (size_t)H;
                float2 v;
                v = *(const float2*)(W0 + c);     aw[kt][g][0] = pack_h2(v.x, v.y);
                v = *(const float2*)(W1 + c);     aw[kt][g][1] = pack_h2(v.x, v.y);
                v = *(const float2*)(W0 + c + 8); aw[kt][g][2] = pack_h2(v.x, v.y);
                v = *(const float2*)(W1 + c + 8); aw[kt][g][3] = pack_h2(v.x, v.y);
            }
        }
    }
    // gate-thread constants + running h (fp32, pre-quantization)
    float hold = 0.0f, bR = 0.f, bZ = 0.f, bN = 0.f;
    if (warp == 0 && lane < IPB) {
        bR = bhh[ig]; bZ = bhh[H + ig]; bN = bhh[2 * H + ig];
    }

#pragma unroll 1
    for (int t = 0; t < T; t++) {
        // prefetch this step's input gates (warp 0; overlaps staging + MMA)
        float gir = 0.f, giz = 0.f, gin = 0.f;
        if (warp == 0 && lane < IPB) {
            const float* git = g_gi + (size_t)t * GH;
            gir = __ldg(git + ig); giz = __ldg(git + H + ig); gin = __ldg(git + 2 * H + ig);
        }

        // stage this warp's 128-col h slice (256B; h(t) readiness guaranteed by
        // the bar2/poll at the end of the previous iteration; t=0 slice is g_ht[0]=0)
        {
            uint2 hv = __ldcg((const uint2*)(g_ht + (size_t)t * H + kbase) + lane);
            *((uint2*)(sh + kbase) + lane) = hv;
        }
        __syncwarp();

        float d[3][4];
#pragma unroll
        for (int g = 0; g < 3; g++) { d[g][0] = d[g][1] = d[g][2] = d[g][3] = 0.f; }
#pragma unroll
        for (int kt = 0; kt < 8; kt++) {
            unsigned bb[2];
            bb[0] = *(const unsigned*)&sh[kbase + kt * 16 + tg * 2];
            bb[1] = *(const unsigned*)&sh[kbase + kt * 16 + tg * 2 + 8];
            mma16816(d[0], aw[kt][0], bb);
            mma16816(d[1], aw[kt][1], bb);
            mma16816(d[2], aw[kt][2], bb);
        }
        const int par = t & 1;
        if (tg == 0) {
#pragma unroll
            for (int g = 0; g < 3; g++) {
                spt[par][g * 16 + qid][warp]     = d[g][0];
                spt[par][g * 16 + qid + 8][warp] = d[g][2];
            }
        }

        if (warp != 0) {
            BAR_ARRIVE_N(1);          // partials published (non-blocking)
            BAR_SYNC_N(2);            // wait until warp 0 confirms h(t+1) ready
        } else {
            BAR_SYNC_N(1);            // wait for all 16 warps' partials
            if (lane < IPB) {
                float ghr = 0.f, ghz = 0.f, ghn = 0.f;
#pragma unroll
                for (int c = 0; c < 4; c++) {
                    float4 v0 = *(const float4*)&spt[par][lane][c * 4];
                    float4 v1 = *(const float4*)&spt[par][16 + lane][c * 4];
                    float4 v2 = *(const float4*)&spt[par][32 + lane][c * 4];
                    ghr += (v0.x + v0.y) + (v0.z + v0.w);
                    ghz += (v1.x + v1.y) + (v1.z + v1.w);
                    ghn += (v2.x + v2.y) + (v2.z + v2.w);
                }
                float rr = 1.0f / (1.0f + expf(-(gir + ghr + bR)));
                float zz = 1.0f / (1.0f + expf(-(giz + ghz + bZ)));
                float nn = tanhf(gin + rr * (ghn + bN));
                float hnew = (1.0f - zz) * nn + zz * hold;
                hold = hnew;
                float other = __shfl_xor_sync(0x0000ffffu, hnew, 1);
                if (!(lane & 1)) {
                    __half2 h2 = __floats2half2_rn(hnew, other);
                    *(__half2*)(g_ht + (size_t)(t + 1) * H + ig) = h2;
                }
            }
            __syncwarp();
            if (lane == 0) {
                bar_arrive(&g_bar[t + 1]);          // release: orders the h stores
                if (t + 1 < T) {
                    while (bar_ld_acq(&g_bar[t + 1]) < target) {}
                }
            }
            __syncwarp();
            BAR_ARRIVE_N(2);          // release the other 15 warps into step t+1
        }
    }
}

// ---------------- 4) final linear: out[n] = h[:,n] @ lin_w + lin_b ----------------
__global__ void k_final(const float* __restrict__ lw, const float* __restrict__ lb,
                        float* __restrict__ out) {
    __shared__ float s[T];
    int n = blockIdx.x, tid = threadIdx.x;   // 256 threads
    s[tid] = __half2float(g_ht[(size_t)(tid + 1) * H + n]);
    __syncthreads();
    if (tid < STEPA) {
        float a = lb[tid];
#pragma unroll 8
        for (int t = 0; t < T; t++) a = fmaf(s[t], lw[t * STEPA + tid], a);
        out[n * STEPA + tid] = a;
    }
}

// ---------------- launch ----------------
extern "C" void kernel_launch(void* const* d_in, const int* in_sizes, int n_in,
                              void* d_out, int out_size) {
    const float* x      = (const float*)d_in[0];
    const int*   ei     = (const int*)  d_in[1];
    const float* ew     = (const float*)d_in[2];
    const float* cnn_w  = (const float*)d_in[3];
    const float* cnn_b  = (const float*)d_in[4];
    const float* gcn_w  = (const float*)d_in[5];
    const float* gcn_b  = (const float*)d_in[6];
    const float* wih    = (const float*)d_in[7];
    const float* whh    = (const float*)d_in[8];
    const float* bih    = (const float*)d_in[9];
    const float* bhh    = (const float*)d_in[10];
    const float* lin_w  = (const float*)d_in[11];
    const float* lin_b  = (const float*)d_in[12];
    float* out = (float*)d_out;

    k_zero0<<<8, 256>>>();                     // replay-safe counter/h0 reset
    k_pre<<<NBLK, PRE_THREADS>>>(x, cnn_w, cnn_b, ei, ew, gcn_w, gcn_b);

    for (int l = 0; l < NLAY; l++) {
        dim3 grid(GH / 128, T / 64);
        k_gi<<<grid, 256>>>(wih + (size_t)l * GH * H, bih + l * GH);
        k_scan<<<NBLK, SCAN_THREADS>>>(whh + (size_t)l * GH * H, bhh + l * GH, l);
    }

    k_final<<<NNODES, T>>>(lin_w, lin_b, out);
}